// round 11
// baseline (speedup 1.0000x reference)
#include <cuda_runtime.h>
#include <cuda_bf16.h>
#include <math.h>
#include <stdint.h>

#define NB 4
#define NS 2048
#define NE 1024
#define BSN (NB * NS)

// ---------------- persistent scratch (no cudaMalloc allowed) ----------------
__device__ __nv_bfloat16 g_Xhi[BSN * NE], g_Xlo[BSN * NE];
__device__ __nv_bfloat16 g_Whi[3 * NE * NE], g_Wlo[3 * NE * NE];
__device__ __nv_bfloat16 g_Qhi[BSN * NE], g_Qlo[BSN * NE];
__device__ __nv_bfloat16 g_Khi[BSN * NE], g_Klo[BSN * NE];
__device__ __nv_bfloat16 g_Vthi[(size_t)NE * BSN], g_Vtlo[(size_t)NE * BSN];
__device__ float         g_P[(size_t)NB * NS * NS];
__device__ __nv_bfloat16 g_Phi[(size_t)NB * NS * NS], g_Plo[(size_t)NB * NS * NS];

// ---------------- helpers ----------------
__device__ __forceinline__ uint32_t smem_u32(const void* p) {
    uint32_t a;
    asm("{ .reg .u64 t; cvta.to.shared.u64 t, %1; cvt.u32.u64 %0, t; }" : "=r"(a) : "l"(p));
    return a;
}
__device__ __forceinline__ void ldsm4(uint32_t* r, uint32_t addr) {
    asm volatile("ldmatrix.sync.aligned.m8n8.x4.shared.b16 {%0,%1,%2,%3}, [%4];"
                 : "=r"(r[0]), "=r"(r[1]), "=r"(r[2]), "=r"(r[3]) : "r"(addr));
}
__device__ __forceinline__ void mma16816(float* c, const uint32_t* a, const uint32_t* b) {
    asm volatile("mma.sync.aligned.m16n8k16.row.col.f32.bf16.bf16.f32 "
                 "{%0,%1,%2,%3}, {%4,%5,%6,%7}, {%8,%9}, {%0,%1,%2,%3};"
                 : "+f"(c[0]), "+f"(c[1]), "+f"(c[2]), "+f"(c[3])
                 : "r"(a[0]), "r"(a[1]), "r"(a[2]), "r"(a[3]), "r"(b[0]), "r"(b[1]));
}
__device__ __forceinline__ void cpa16(uint32_t s, const void* g) {
    asm volatile("cp.async.cg.shared.global [%0], [%1], 16;" :: "r"(s), "l"(g));
}
#define CP_COMMIT() asm volatile("cp.async.commit_group;" ::: "memory")
#define CP_WAIT(N)  asm volatile("cp.async.wait_group %0;" :: "n"(N) : "memory")

__device__ __forceinline__ uint32_t pack_bf2(float a, float b) {
    unsigned short ua = __bfloat16_as_ushort(__float2bfloat16(a));
    unsigned short ub = __bfloat16_as_ushort(__float2bfloat16(b));
    return (uint32_t)ua | ((uint32_t)ub << 16);
}
__device__ __forceinline__ void split2(float a, float b, uint32_t& h, uint32_t& l) {
    h = pack_bf2(a, b);
    float ha = __uint_as_float(h << 16);
    float hb = __uint_as_float(h & 0xFFFF0000u);
    l = pack_bf2(a - ha, b - hb);
}

// smem: BK=32 -> unpadded 64 B rows with XOR quad swizzle (q ^= (row>>1)&3).
#define T_A_HI 0
#define T_A_LO 8192
#define T_B_HI 16384
#define T_B_LO 24576
#define STAGE  32768
#define NSTAGE 3
#define SMEM_TOTAL (NSTAGE * STAGE)   // 98304 B per CTA -> 2 CTAs/SM

// ---------------------------------------------------------------------------
// HMMA GEMM, bf16 hi/lo 3-term split, NT: C = alpha*A*B^T (+bias)
// CTA tile 128x128, BK=32, 128 threads (4 warps 2Mx2N), warp tile 64x64.
// 3-stage cp.async pipeline, per-kh full LDSM hoist, strength-reduced staging.
// BIAS: 0 none, 1 bias[col], 2 bias[row].  OUTMODE: 0 fp32 C, 1 bf16 hi/lo C.
// DUAL: blockIdx.z selects operand set {B,bias,C} vs {B2,bias2,C2}.
// ---------------------------------------------------------------------------
template <int BIAS, int OUTMODE, int DUAL>
__global__ void __launch_bounds__(128, 2)
tcgemm(const __nv_bfloat16* __restrict__ Ahi, const __nv_bfloat16* __restrict__ Alo,
       const __nv_bfloat16* __restrict__ Bhi, const __nv_bfloat16* __restrict__ Blo,
       const __nv_bfloat16* __restrict__ Bhi2, const __nv_bfloat16* __restrict__ Blo2,
       const float* __restrict__ bias, const float* __restrict__ bias2,
       float* __restrict__ C,
       __nv_bfloat16* __restrict__ Chi, __nv_bfloat16* __restrict__ Clo,
       __nv_bfloat16* __restrict__ Chi2, __nv_bfloat16* __restrict__ Clo2,
       int lda, int ldb, int ldc, int Kdim,
       long long sA, long long sB, long long sC, float alpha)
{
    extern __shared__ char smem[];
    const uint32_t sb = smem_u32(smem);
    const int tid = threadIdx.x;
    const int lane = tid & 31;
    const int wid = tid >> 5;
    const int warpM = (wid & 1) * 64;     // 2 warps in M
    const int warpN = (wid >> 1) * 64;    // 2 warps in N

    const __nv_bfloat16* pBhi = Bhi;
    const __nv_bfloat16* pBlo = Blo;
    const float* pbias = bias;
    __nv_bfloat16* pChi = Chi;
    __nv_bfloat16* pClo = Clo;
    if (DUAL && blockIdx.z == 1) {
        pBhi = Bhi2; pBlo = Blo2; pbias = bias2; pChi = Chi2; pClo = Clo2;
    }
    const long long zb = DUAL ? 0 : (long long)blockIdx.z;

    const long long aoff = zb * sA + (long long)(blockIdx.y * 128) * lda;
    const long long boff = zb * sB + (long long)(blockIdx.x * 128) * ldb;

    float acc[4][8][4];
#pragma unroll
    for (int m = 0; m < 4; m++)
#pragma unroll
        for (int n = 0; n < 8; n++)
#pragma unroll
            for (int q = 0; q < 4; q++) acc[m][n][q] = 0.f;

    // ---- strength-reduced staging state ----
    // swizzle term (r>>1)&3 is invariant under r += 32, so smem offset is
    // so0 + p*2048; gmem pointers advance +32 elements per issued chunk.
    const int r0 = tid >> 2, q0 = tid & 3;
    const uint32_t so0 = (uint32_t)(r0 * 64 + ((q0 ^ ((r0 >> 1) & 3)) * 16));
    const __nv_bfloat16* gAh = Ahi + aoff + (long long)r0 * lda + q0 * 8;
    const __nv_bfloat16* gAl = Alo + aoff + (long long)r0 * lda + q0 * 8;
    const __nv_bfloat16* gBh = pBhi + boff + (long long)r0 * ldb + q0 * 8;
    const __nv_bfloat16* gBl = pBlo + boff + (long long)r0 * ldb + q0 * 8;
    const long long stepA = 32LL * lda;
    const long long stepB = 32LL * ldb;

    auto issueStage = [&](uint32_t st) {
#pragma unroll
        for (int p = 0; p < 4; p++) {
            const uint32_t so = so0 + (uint32_t)(p * 2048);
            cpa16(st + T_A_HI + so, gAh + p * stepA);
            cpa16(st + T_A_LO + so, gAl + p * stepA);
            cpa16(st + T_B_HI + so, gBh + p * stepB);
            cpa16(st + T_B_LO + so, gBl + p * stepB);
        }
        gAh += 32; gAl += 32; gBh += 32; gBl += 32;
        CP_COMMIT();
    };

    // ldmatrix lane addressing (constants per thread)
    const int lr = lane & 15;
    const int lq = lane >> 4;
    const int lsw = (lr >> 1) & 3;
    const uint32_t rowA = (uint32_t)(warpM + lr);
    const uint32_t rowB = (uint32_t)(warpN + lr);

    auto compute = [&](uint32_t stb) {
#pragma unroll
        for (int kh = 0; kh < 2; kh++) {
            const uint32_t qb = (uint32_t)(((kh * 2 + lq) ^ lsw) * 16);
            uint32_t ahi[4][4], alo[4][4], bhi[8][2], blo[8][2];
            // full LDSM burst: one latency wall per kh, then 96 clean MMAs
#pragma unroll
            for (int mt = 0; mt < 4; mt++) {
                ldsm4(ahi[mt], stb + T_A_HI + (rowA + mt * 16) * 64 + qb);
                ldsm4(alo[mt], stb + T_A_LO + (rowA + mt * 16) * 64 + qb);
            }
#pragma unroll
            for (int np = 0; np < 4; np++) {
                uint32_t t[4];
                ldsm4(t, stb + T_B_HI + (rowB + np * 16) * 64 + qb);
                bhi[2 * np][0] = t[0]; bhi[2 * np][1] = t[2];
                bhi[2 * np + 1][0] = t[1]; bhi[2 * np + 1][1] = t[3];
                ldsm4(t, stb + T_B_LO + (rowB + np * 16) * 64 + qb);
                blo[2 * np][0] = t[0]; blo[2 * np][1] = t[2];
                blo[2 * np + 1][0] = t[1]; blo[2 * np + 1][1] = t[3];
            }
#pragma unroll
            for (int mt = 0; mt < 4; mt++)
#pragma unroll
                for (int nt = 0; nt < 8; nt++) mma16816(acc[mt][nt], ahi[mt], bhi[nt]);
#pragma unroll
            for (int mt = 0; mt < 4; mt++)
#pragma unroll
                for (int nt = 0; nt < 8; nt++) mma16816(acc[mt][nt], ahi[mt], blo[nt]);
#pragma unroll
            for (int mt = 0; mt < 4; mt++)
#pragma unroll
                for (int nt = 0; nt < 8; nt++) mma16816(acc[mt][nt], alo[mt], bhi[nt]);
        }
    };

    const int CH = Kdim >> 5;      // BK = 32
    const uint32_t sTop = sb + (NSTAGE - 1) * STAGE;
    uint32_t stW = sb, stR = sb;

    issueStage(stW); stW += STAGE;
    issueStage(stW); stW += STAGE;

    for (int c = 0; c < CH; c++) {
        if (c + 1 < CH) { CP_WAIT(1); } else { CP_WAIT(0); }
        __syncthreads();
        if (c + 2 < CH) {
            issueStage(stW);
            stW = (stW == sTop) ? sb : stW + STAGE;
        }
        compute(stR);
        stR = (stR == sTop) ? sb : stR + STAGE;
        // no tail sync: issue at iter c targets buffer (c-1)%3, which all
        // warps finished computing before this iteration's head sync.
    }

    // ---- epilogue ----
    const int g = lane >> 2, tg = lane & 3;
#pragma unroll
    for (int mt = 0; mt < 4; mt++) {
        const int row = blockIdx.y * 128 + warpM + mt * 16 + g;
        float rb0 = 0.f, rb8 = 0.f;
        if (BIAS == 2) { rb0 = pbias[row]; rb8 = pbias[row + 8]; }
#pragma unroll
        for (int nt = 0; nt < 8; nt++) {
            const int col = blockIdx.x * 128 + warpN + nt * 8 + tg * 2;
            float b0 = 0.f, b1 = 0.f;
            if (BIAS == 1) { b0 = pbias[col]; b1 = pbias[col + 1]; }
            float c0 = acc[mt][nt][0] * alpha;
            float c1 = acc[mt][nt][1] * alpha;
            float c2 = acc[mt][nt][2] * alpha;
            float c3 = acc[mt][nt][3] * alpha;
            if (BIAS == 1) { c0 += b0; c1 += b1; c2 += b0; c3 += b1; }
            if (BIAS == 2) { c0 += rb0; c1 += rb0; c2 += rb8; c3 += rb8; }
            const long long i0 = zb * sC + (long long)row * ldc + col;
            const long long i1 = i0 + (long long)8 * ldc;
            if (OUTMODE == 0) {
                *(float2*)(C + i0) = make_float2(c0, c1);
                *(float2*)(C + i1) = make_float2(c2, c3);
            } else {
                uint32_t h, l;
                split2(c0, c1, h, l);
                *(uint32_t*)(pChi + i0) = h; *(uint32_t*)(pClo + i0) = l;
                split2(c2, c3, h, l);
                *(uint32_t*)(pChi + i1) = h; *(uint32_t*)(pClo + i1) = l;
            }
        }
    }
}

// ---------------------------------------------------------------------------
// Fused fp32 -> bf16 hi/lo split over [X | Wk | Wq | Wv] (one launch).
// ---------------------------------------------------------------------------
#define X4  (BSN * NE / 4)
#define W4  (NE * NE / 4)
__global__ __launch_bounds__(256)
void splitAll(const float* __restrict__ X,
              const float* __restrict__ Wk, const float* __restrict__ Wq,
              const float* __restrict__ Wv,
              __nv_bfloat16* __restrict__ Xhi, __nv_bfloat16* __restrict__ Xlo,
              __nv_bfloat16* __restrict__ Whi, __nv_bfloat16* __restrict__ Wlo)
{
    const int i = blockIdx.x * 256 + threadIdx.x;
    const float* src;
    __nv_bfloat16 *hi, *lo;
    int j;
    if (i < X4)                { src = X;  hi = Xhi;          lo = Xlo;          j = i; }
    else if (i < X4 + W4)      { src = Wk; hi = Whi;          lo = Wlo;          j = i - X4; }
    else if (i < X4 + 2 * W4)  { src = Wq; hi = Whi + NE*NE;  lo = Wlo + NE*NE;  j = i - X4 - W4; }
    else                       { src = Wv; hi = Whi + 2*NE*NE; lo = Wlo + 2*NE*NE; j = i - X4 - 2*W4; }
    const float4 v = ((const float4*)src)[j];
    uint32_t h01, l01, h23, l23;
    split2(v.x, v.y, h01, l01);
    split2(v.z, v.w, h23, l23);
    ((uint2*)hi)[j] = make_uint2(h01, h23);
    ((uint2*)lo)[j] = make_uint2(l01, l23);
}

// ---------------------------------------------------------------------------
// Row softmax over 2048, emits bf16 hi/lo. One block (256 thr) per row.
// ---------------------------------------------------------------------------
__global__ __launch_bounds__(256)
void softmax2048(const float* __restrict__ P, __nv_bfloat16* __restrict__ Phi,
                 __nv_bfloat16* __restrict__ Plo)
{
    __shared__ float red[32];
    const float* p = P + (long long)blockIdx.x * NS;
    const int tid = threadIdx.x;

    float v[8];
    {
        const float4 a = *(const float4*)(p + tid * 8);
        const float4 b = *(const float4*)(p + tid * 8 + 4);
        v[0] = a.x; v[1] = a.y; v[2] = a.z; v[3] = a.w;
        v[4] = b.x; v[5] = b.y; v[6] = b.z; v[7] = b.w;
    }

    float m = v[0];
#pragma unroll
    for (int i = 1; i < 8; i++) m = fmaxf(m, v[i]);
#pragma unroll
    for (int o = 16; o > 0; o >>= 1) m = fmaxf(m, __shfl_xor_sync(0xffffffffu, m, o));
    if ((tid & 31) == 0) red[tid >> 5] = m;
    __syncthreads();
    if (tid < 32) {
        float t = (tid < 8) ? red[tid] : -INFINITY;
#pragma unroll
        for (int o = 4; o > 0; o >>= 1) t = fmaxf(t, __shfl_xor_sync(0xffffffffu, t, o));
        if (tid == 0) red[0] = t;
    }
    __syncthreads();
    m = red[0];
    __syncthreads();

    float s = 0.f;
#pragma unroll
    for (int i = 0; i < 8; i++) { v[i] = __expf(v[i] - m); s += v[i]; }
#pragma unroll
    for (int o = 16; o > 0; o >>= 1) s += __shfl_xor_sync(0xffffffffu, s, o);
    if ((tid & 31) == 0) red[tid >> 5] = s;
    __syncthreads();
    if (tid < 32) {
        float t = (tid < 8) ? red[tid] : 0.f;
#pragma unroll
        for (int o = 4; o > 0; o >>= 1) t += __shfl_xor_sync(0xffffffffu, t, o);
        if (tid == 0) red[0] = t;
    }
    __syncthreads();
    const float inv = 1.f / red[0];

    uint4 H, L;
    split2(v[0] * inv, v[1] * inv, H.x, L.x);
    split2(v[2] * inv, v[3] * inv, H.y, L.y);
    split2(v[4] * inv, v[5] * inv, H.z, L.z);
    split2(v[6] * inv, v[7] * inv, H.w, L.w);
    const long long o = (long long)blockIdx.x * NS + tid * 8;
    *(uint4*)(Phi + o) = H;
    *(uint4*)(Plo + o) = L;
}

// ---------------------------------------------------------------------------
// Launcher.
// ---------------------------------------------------------------------------
extern "C" void kernel_launch(void* const* d_in, const int* in_sizes, int n_in,
                              void* d_out, int out_size)
{
    const float* X  = (const float*)d_in[0];
    const float* Wk = (const float*)d_in[1];
    const float* bk = (const float*)d_in[2];
    const float* Wq = (const float*)d_in[3];
    const float* bq = (const float*)d_in[4];
    const float* Wv = (const float*)d_in[5];
    const float* bv = (const float*)d_in[6];
    float* Y = (float*)d_out;

    __nv_bfloat16 *Xhi, *Xlo, *Whi, *Wlo, *Qhi, *Qlo, *Khi, *Klo, *Vthi, *Vtlo, *Phi, *Plo;
    float* Pp;
    cudaGetSymbolAddress((void**)&Xhi, g_Xhi);   cudaGetSymbolAddress((void**)&Xlo, g_Xlo);
    cudaGetSymbolAddress((void**)&Whi, g_Whi);   cudaGetSymbolAddress((void**)&Wlo, g_Wlo);
    cudaGetSymbolAddress((void**)&Qhi, g_Qhi);   cudaGetSymbolAddress((void**)&Qlo, g_Qlo);
    cudaGetSymbolAddress((void**)&Khi, g_Khi);   cudaGetSymbolAddress((void**)&Klo, g_Klo);
    cudaGetSymbolAddress((void**)&Vthi, g_Vthi); cudaGetSymbolAddress((void**)&Vtlo, g_Vtlo);
    cudaGetSymbolAddress((void**)&Phi, g_Phi);   cudaGetSymbolAddress((void**)&Plo, g_Plo);
    cudaGetSymbolAddress((void**)&Pp, g_P);

    cudaFuncSetAttribute(tcgemm<0, 0, 0>, cudaFuncAttributeMaxDynamicSharedMemorySize, SMEM_TOTAL);
    cudaFuncSetAttribute(tcgemm<1, 1, 1>, cudaFuncAttributeMaxDynamicSharedMemorySize, SMEM_TOTAL);
    cudaFuncSetAttribute(tcgemm<2, 1, 0>, cudaFuncAttributeMaxDynamicSharedMemorySize, SMEM_TOTAL);

    const int WN = NE * NE;
    const dim3 blk(128);

    // one fused split launch: X, Wk, Wq, Wv
    splitAll<<<(X4 + 3 * W4) / 256, 256>>>(X, Wk, Wq, Wv, Xhi, Xlo, Whi, Wlo);

    // K + Q projections fused (z=0 -> K, z=1 -> Q)
    {
        dim3 grid(NE / 128, BSN / 128, 2);
        tcgemm<1, 1, 1><<<grid, blk, SMEM_TOTAL>>>(
            Xhi, Xlo,
            Whi, Wlo, Whi + WN, Wlo + WN,
            bk, bq,
            nullptr, Khi, Klo, Qhi, Qlo,
            NE, NE, NE, NE, 0, 0, 0, 1.f);
    }
    // Vt = Wv @ X^T + bv(row) -> bf16 hi/lo [E, B*S]
    {
        dim3 grid(BSN / 128, NE / 128, 1);
        tcgemm<2, 1, 0><<<grid, blk, SMEM_TOTAL>>>(
            Whi + 2 * WN, Wlo + 2 * WN, Xhi, Xlo, nullptr, nullptr,
            bv, nullptr,
            nullptr, Vthi, Vtlo, nullptr, nullptr,
            NE, NE, BSN, NE, 0, 0, 0, 1.f);
    }
    // Scores: P[b,j,i] = Q_j . K_i / sqrt(S)  (M=N=2048, batched)
    {
        dim3 grid(NS / 128, NS / 128, NB);
        const float alpha = rsqrtf((float)NS);
        tcgemm<0, 0, 0><<<grid, blk, SMEM_TOTAL>>>(
            Qhi, Qlo, Khi, Klo, nullptr, nullptr,
            nullptr, nullptr,
            Pp, nullptr, nullptr, nullptr, nullptr,
            NE, NE, NS, NE,
            (long long)NS * NE, (long long)NS * NE, (long long)NS * NS, alpha);
    }
    // Softmax over key index i -> bf16 hi/lo
    softmax2048<<<NB * NS, 256>>>(Pp, Phi, Plo);

    // Y = P @ Vt^T  (M=2048, N=1024, K=2048)
    {
        dim3 grid(NE / 128, NS / 128, NB);
        tcgemm<0, 0, 0><<<grid, blk, SMEM_TOTAL>>>(
            Phi, Plo, Vthi, Vtlo, nullptr, nullptr,
            nullptr, nullptr,
            Y, nullptr, nullptr, nullptr, nullptr,
            NS, BSN, NE, NS,
            (long long)NS * NS, (long long)NS, (long long)NS * NE, 1.f);
    }
}

// round 12
// speedup vs baseline: 1.0439x; 1.0439x over previous
#include <cuda_runtime.h>
#include <cuda_bf16.h>
#include <math.h>
#include <stdint.h>

#define NB 4
#define NS 2048
#define NE 1024
#define BSN (NB * NS)

// ---------------- persistent scratch (no cudaMalloc allowed) ----------------
__device__ __nv_bfloat16 g_Xhi[BSN * NE], g_Xlo[BSN * NE];
__device__ __nv_bfloat16 g_Whi[3 * NE * NE], g_Wlo[3 * NE * NE];
__device__ __nv_bfloat16 g_Qhi[BSN * NE], g_Qlo[BSN * NE];
__device__ __nv_bfloat16 g_Khi[BSN * NE], g_Klo[BSN * NE];
__device__ __nv_bfloat16 g_Vthi[(size_t)NE * BSN], g_Vtlo[(size_t)NE * BSN];
__device__ float         g_P[(size_t)NB * NS * NS];
__device__ __nv_bfloat16 g_Phi[(size_t)NB * NS * NS], g_Plo[(size_t)NB * NS * NS];

// ---------------- helpers ----------------
__device__ __forceinline__ uint32_t smem_u32(const void* p) {
    uint32_t a;
    asm("{ .reg .u64 t; cvta.to.shared.u64 t, %1; cvt.u32.u64 %0, t; }" : "=r"(a) : "l"(p));
    return a;
}
__device__ __forceinline__ void ldsm4(uint32_t* r, uint32_t addr) {
    asm volatile("ldmatrix.sync.aligned.m8n8.x4.shared.b16 {%0,%1,%2,%3}, [%4];"
                 : "=r"(r[0]), "=r"(r[1]), "=r"(r[2]), "=r"(r[3]) : "r"(addr));
}
__device__ __forceinline__ void mma16816(float* c, const uint32_t* a, const uint32_t* b) {
    asm volatile("mma.sync.aligned.m16n8k16.row.col.f32.bf16.bf16.f32 "
                 "{%0,%1,%2,%3}, {%4,%5,%6,%7}, {%8,%9}, {%0,%1,%2,%3};"
                 : "+f"(c[0]), "+f"(c[1]), "+f"(c[2]), "+f"(c[3])
                 : "r"(a[0]), "r"(a[1]), "r"(a[2]), "r"(a[3]), "r"(b[0]), "r"(b[1]));
}
__device__ __forceinline__ void cpa16(uint32_t s, const void* g) {
    asm volatile("cp.async.cg.shared.global [%0], [%1], 16;" :: "r"(s), "l"(g));
}
#define CP_COMMIT() asm volatile("cp.async.commit_group;" ::: "memory")
#define CP_WAIT(N)  asm volatile("cp.async.wait_group %0;" :: "n"(N) : "memory")

__device__ __forceinline__ uint32_t pack_bf2(float a, float b) {
    unsigned short ua = __bfloat16_as_ushort(__float2bfloat16(a));
    unsigned short ub = __bfloat16_as_ushort(__float2bfloat16(b));
    return (uint32_t)ua | ((uint32_t)ub << 16);
}
__device__ __forceinline__ void split2(float a, float b, uint32_t& h, uint32_t& l) {
    h = pack_bf2(a, b);
    float ha = __uint_as_float(h << 16);
    float hb = __uint_as_float(h & 0xFFFF0000u);
    l = pack_bf2(a - ha, b - hb);
}

// smem: BK=32 -> unpadded 64 B rows with XOR quad swizzle (q ^= (row>>1)&3).
#define T_A_HI 0
#define T_A_LO 8192
#define T_B_HI 16384
#define T_B_LO 24576
#define STAGE  32768
#define NSTAGE 3
#define SMEM_TOTAL (NSTAGE * STAGE)   // 98304 B per CTA -> 2 CTAs/SM

// ---------------------------------------------------------------------------
// GEMM body: C = alpha*A*B^T (+bias), bf16 hi/lo 3-term split.
// CTA tile 128x128, BK=32, 128 threads (4 warps 2Mx2N), warp tile 64x64.
// 3-stage cp.async pipeline; staging issued BETWEEN kh0 and kh1 so the
// cp.async burst interleaves with MMA pipe work instead of the post-sync
// fragment loads. biasMode: 0 none, 1 bias[col], 2 bias[row] (runtime,
// epilogue-only). OUTMODE: 0 fp32 C, 1 bf16 hi/lo C.
// A/B pointers are pre-offset to the CTA tile.
// ---------------------------------------------------------------------------
template <int OUTMODE>
__device__ __forceinline__ void gemm_body(
    const __nv_bfloat16* __restrict__ Ahi, const __nv_bfloat16* __restrict__ Alo,
    const __nv_bfloat16* __restrict__ Bhi, const __nv_bfloat16* __restrict__ Blo,
    int lda, int ldb, int Kdim,
    const float* __restrict__ bias, int biasMode,
    float* __restrict__ C, __nv_bfloat16* __restrict__ Chi, __nv_bfloat16* __restrict__ Clo,
    long long cbase, int ldc, int row0, int col0, float alpha)
{
    extern __shared__ char smem[];
    const uint32_t sb = smem_u32(smem);
    const int tid = threadIdx.x;
    const int lane = tid & 31;
    const int wid = tid >> 5;
    const int warpM = (wid & 1) * 64;
    const int warpN = (wid >> 1) * 64;

    float acc[4][8][4];
#pragma unroll
    for (int m = 0; m < 4; m++)
#pragma unroll
        for (int n = 0; n < 8; n++)
#pragma unroll
            for (int q = 0; q < 4; q++) acc[m][n][q] = 0.f;

    // strength-reduced staging state
    const int r0 = tid >> 2, q0 = tid & 3;
    const uint32_t so0 = (uint32_t)(r0 * 64 + ((q0 ^ ((r0 >> 1) & 3)) * 16));
    const __nv_bfloat16* gAh = Ahi + (long long)r0 * lda + q0 * 8;
    const __nv_bfloat16* gAl = Alo + (long long)r0 * lda + q0 * 8;
    const __nv_bfloat16* gBh = Bhi + (long long)r0 * ldb + q0 * 8;
    const __nv_bfloat16* gBl = Blo + (long long)r0 * ldb + q0 * 8;
    const long long stepA = 32LL * lda;
    const long long stepB = 32LL * ldb;

    auto issueStage = [&](uint32_t st) {
#pragma unroll
        for (int p = 0; p < 4; p++) {
            const uint32_t so = so0 + (uint32_t)(p * 2048);
            cpa16(st + T_A_HI + so, gAh + p * stepA);
            cpa16(st + T_A_LO + so, gAl + p * stepA);
            cpa16(st + T_B_HI + so, gBh + p * stepB);
            cpa16(st + T_B_LO + so, gBl + p * stepB);
        }
        gAh += 32; gAl += 32; gBh += 32; gBl += 32;
        CP_COMMIT();
    };

    // ldmatrix lane addressing
    const int lr = lane & 15;
    const int lq = lane >> 4;
    const int lsw = (lr >> 1) & 3;
    const uint32_t rowA = (uint32_t)(warpM + lr);
    const uint32_t rowB = (uint32_t)(warpN + lr);

    // one kh half-chunk: 16 LDSM + 96 MMAs
    auto khPart = [&](uint32_t stb, int kh) {
        const uint32_t qb = (uint32_t)(((kh * 2 + lq) ^ lsw) * 16);
        uint32_t ahi[4][4], alo[4][4], bhi[8][2], blo[8][2];
#pragma unroll
        for (int mt = 0; mt < 4; mt++) {
            ldsm4(ahi[mt], stb + T_A_HI + (rowA + mt * 16) * 64 + qb);
            ldsm4(alo[mt], stb + T_A_LO + (rowA + mt * 16) * 64 + qb);
        }
#pragma unroll
        for (int np = 0; np < 4; np++) {
            uint32_t t[4];
            ldsm4(t, stb + T_B_HI + (rowB + np * 16) * 64 + qb);
            bhi[2 * np][0] = t[0]; bhi[2 * np][1] = t[2];
            bhi[2 * np + 1][0] = t[1]; bhi[2 * np + 1][1] = t[3];
            ldsm4(t, stb + T_B_LO + (rowB + np * 16) * 64 + qb);
            blo[2 * np][0] = t[0]; blo[2 * np][1] = t[2];
            blo[2 * np + 1][0] = t[1]; blo[2 * np + 1][1] = t[3];
        }
#pragma unroll
        for (int mt = 0; mt < 4; mt++)
#pragma unroll
            for (int nt = 0; nt < 8; nt++) mma16816(acc[mt][nt], ahi[mt], bhi[nt]);
#pragma unroll
        for (int mt = 0; mt < 4; mt++)
#pragma unroll
            for (int nt = 0; nt < 8; nt++) mma16816(acc[mt][nt], ahi[mt], blo[nt]);
#pragma unroll
        for (int mt = 0; mt < 4; mt++)
#pragma unroll
            for (int nt = 0; nt < 8; nt++) mma16816(acc[mt][nt], alo[mt], bhi[nt]);
    };

    const int CH = Kdim >> 5;      // BK = 32
    const uint32_t sTop = sb + (NSTAGE - 1) * STAGE;
    uint32_t stW = sb, stR = sb;

    issueStage(stW); stW += STAGE;
    issueStage(stW); stW += STAGE;

    for (int c = 0; c < CH; c++) {
        if (c + 1 < CH) { CP_WAIT(1); } else { CP_WAIT(0); }
        __syncthreads();
        khPart(stR, 0);                 // MMAs first: tensor pipe fills
        if (c + 2 < CH) {               // staging burst hides under MMA drain
            issueStage(stW);
            stW = (stW == sTop) ? sb : stW + STAGE;
        }
        khPart(stR, 1);
        stR = (stR == sTop) ? sb : stR + STAGE;
        // no tail sync: issue at iter c targets buffer (c-1)%3, which all
        // warps finished computing before this iteration's head sync.
    }

    // ---- epilogue ----
    const int g = lane >> 2, tg = lane & 3;
#pragma unroll
    for (int mt = 0; mt < 4; mt++) {
        const int row = row0 + warpM + mt * 16 + g;
        float rb0 = 0.f, rb8 = 0.f;
        if (biasMode == 2) { rb0 = bias[row]; rb8 = bias[row + 8]; }
#pragma unroll
        for (int nt = 0; nt < 8; nt++) {
            const int col = col0 + warpN + nt * 8 + tg * 2;
            float c0 = acc[mt][nt][0] * alpha;
            float c1 = acc[mt][nt][1] * alpha;
            float c2 = acc[mt][nt][2] * alpha;
            float c3 = acc[mt][nt][3] * alpha;
            if (biasMode == 1) {
                const float b0 = bias[col], b1 = bias[col + 1];
                c0 += b0; c1 += b1; c2 += b0; c3 += b1;
            } else if (biasMode == 2) {
                c0 += rb0; c1 += rb0; c2 += rb8; c3 += rb8;
            }
            const long long i0 = cbase + (long long)row * ldc + col;
            const long long i1 = i0 + (long long)8 * ldc;
            if (OUTMODE == 0) {
                *(float2*)(C + i0) = make_float2(c0, c1);
                *(float2*)(C + i1) = make_float2(c2, c3);
            } else {
                uint32_t h, l;
                split2(c0, c1, h, l);
                *(uint32_t*)(Chi + i0) = h; *(uint32_t*)(Clo + i0) = l;
                split2(c2, c3, h, l);
                *(uint32_t*)(Chi + i1) = h; *(uint32_t*)(Clo + i1) = l;
            }
        }
    }
}

// ---------------------------------------------------------------------------
// Fused projection kernel: z=0 -> K, z=1 -> Q, z=2 -> Vt (remapped tiles).
// grid (8, 64, 3).
// ---------------------------------------------------------------------------
__global__ void __launch_bounds__(128, 2)
gemm_proj3(const __nv_bfloat16* __restrict__ Xhi, const __nv_bfloat16* __restrict__ Xlo,
           const __nv_bfloat16* __restrict__ Whi, const __nv_bfloat16* __restrict__ Wlo,
           const float* __restrict__ bk, const float* __restrict__ bq,
           const float* __restrict__ bv,
           __nv_bfloat16* __restrict__ Khi, __nv_bfloat16* __restrict__ Klo,
           __nv_bfloat16* __restrict__ Qhi, __nv_bfloat16* __restrict__ Qlo,
           __nv_bfloat16* __restrict__ Vthi, __nv_bfloat16* __restrict__ Vtlo)
{
    const int WN = NE * NE;
    const int z = blockIdx.z;
    if (z < 2) {
        // K or Q = X @ W^T + b(col): M = BSN, N = NE
        const int row0 = blockIdx.y * 128;
        const int col0 = blockIdx.x * 128;
        const long long aoff = (long long)row0 * NE;
        const long long boff = (long long)z * WN + (long long)col0 * NE;
        gemm_body<1>(Xhi + aoff, Xlo + aoff, Whi + boff, Wlo + boff,
                     NE, NE, NE,
                     (z == 0) ? bk : bq, 1,
                     nullptr,
                     (z == 0) ? Khi : Qhi, (z == 0) ? Klo : Qlo,
                     0, NE, row0, col0, 1.f);
    } else {
        // Vt = Wv @ X^T + bv(row): M = NE, N = BSN
        const int tx = blockIdx.x + (blockIdx.y & 7) * 8;  // 0..63 (N tiles)
        const int ty = blockIdx.y >> 3;                    // 0..7  (M tiles)
        const int row0 = ty * 128;
        const int col0 = tx * 128;
        const long long aoff = 2LL * WN + (long long)row0 * NE;
        const long long boff = (long long)col0 * NE;
        gemm_body<1>(Whi + aoff, Wlo + aoff, Xhi + boff, Xlo + boff,
                     NE, NE, NE,
                     bv, 2,
                     nullptr, Vthi, Vtlo,
                     0, BSN, row0, col0, 1.f);
    }
}

// ---------------------------------------------------------------------------
// Plain batched NT GEMM wrapper (fp32 out, no bias).
// ---------------------------------------------------------------------------
__global__ void __launch_bounds__(128, 2)
gemm_nt(const __nv_bfloat16* __restrict__ Ahi, const __nv_bfloat16* __restrict__ Alo,
        const __nv_bfloat16* __restrict__ Bhi, const __nv_bfloat16* __restrict__ Blo,
        float* __restrict__ C,
        int lda, int ldb, int ldc, int Kdim,
        long long sA, long long sB, long long sC, float alpha)
{
    const int row0 = blockIdx.y * 128;
    const int col0 = blockIdx.x * 128;
    const long long aoff = (long long)blockIdx.z * sA + (long long)row0 * lda;
    const long long boff = (long long)blockIdx.z * sB + (long long)col0 * ldb;
    gemm_body<0>(Ahi + aoff, Alo + aoff, Bhi + boff, Blo + boff,
                 lda, ldb, Kdim,
                 nullptr, 0,
                 C, nullptr, nullptr,
                 (long long)blockIdx.z * sC, ldc, row0, col0, alpha);
}

// ---------------------------------------------------------------------------
// Fused fp32 -> bf16 hi/lo split over [X | Wk | Wq | Wv] (one launch).
// ---------------------------------------------------------------------------
#define X4  (BSN * NE / 4)
#define W4  (NE * NE / 4)
__global__ __launch_bounds__(256)
void splitAll(const float* __restrict__ X,
              const float* __restrict__ Wk, const float* __restrict__ Wq,
              const float* __restrict__ Wv,
              __nv_bfloat16* __restrict__ Xhi, __nv_bfloat16* __restrict__ Xlo,
              __nv_bfloat16* __restrict__ Whi, __nv_bfloat16* __restrict__ Wlo)
{
    const int i = blockIdx.x * 256 + threadIdx.x;
    const float* src;
    __nv_bfloat16 *hi, *lo;
    int j;
    if (i < X4)                { src = X;  hi = Xhi;          lo = Xlo;          j = i; }
    else if (i < X4 + W4)      { src = Wk; hi = Whi;          lo = Wlo;          j = i - X4; }
    else if (i < X4 + 2 * W4)  { src = Wq; hi = Whi + NE*NE;  lo = Wlo + NE*NE;  j = i - X4 - W4; }
    else                       { src = Wv; hi = Whi + 2*NE*NE; lo = Wlo + 2*NE*NE; j = i - X4 - 2*W4; }
    const float4 v = ((const float4*)src)[j];
    uint32_t h01, l01, h23, l23;
    split2(v.x, v.y, h01, l01);
    split2(v.z, v.w, h23, l23);
    ((uint2*)hi)[j] = make_uint2(h01, h23);
    ((uint2*)lo)[j] = make_uint2(l01, l23);
}

// ---------------------------------------------------------------------------
// Row softmax over 2048, emits bf16 hi/lo. One block (256 thr) per row.
// ---------------------------------------------------------------------------
__global__ __launch_bounds__(256)
void softmax2048(const float* __restrict__ P, __nv_bfloat16* __restrict__ Phi,
                 __nv_bfloat16* __restrict__ Plo)
{
    __shared__ float red[32];
    const float* p = P + (long long)blockIdx.x * NS;
    const int tid = threadIdx.x;

    float v[8];
    {
        const float4 a = *(const float4*)(p + tid * 8);
        const float4 b = *(const float4*)(p + tid * 8 + 4);
        v[0] = a.x; v[1] = a.y; v[2] = a.z; v[3] = a.w;
        v[4] = b.x; v[5] = b.y; v[6] = b.z; v[7] = b.w;
    }

    float m = v[0];
#pragma unroll
    for (int i = 1; i < 8; i++) m = fmaxf(m, v[i]);
#pragma unroll
    for (int o = 16; o > 0; o >>= 1) m = fmaxf(m, __shfl_xor_sync(0xffffffffu, m, o));
    if ((tid & 31) == 0) red[tid >> 5] = m;
    __syncthreads();
    if (tid < 32) {
        float t = (tid < 8) ? red[tid] : -INFINITY;
#pragma unroll
        for (int o = 4; o > 0; o >>= 1) t = fmaxf(t, __shfl_xor_sync(0xffffffffu, t, o));
        if (tid == 0) red[0] = t;
    }
    __syncthreads();
    m = red[0];
    __syncthreads();

    float s = 0.f;
#pragma unroll
    for (int i = 0; i < 8; i++) { v[i] = __expf(v[i] - m); s += v[i]; }
#pragma unroll
    for (int o = 16; o > 0; o >>= 1) s += __shfl_xor_sync(0xffffffffu, s, o);
    if ((tid & 31) == 0) red[tid >> 5] = s;
    __syncthreads();
    if (tid < 32) {
        float t = (tid < 8) ? red[tid] : 0.f;
#pragma unroll
        for (int o = 4; o > 0; o >>= 1) t += __shfl_xor_sync(0xffffffffu, t, o);
        if (tid == 0) red[0] = t;
    }
    __syncthreads();
    const float inv = 1.f / red[0];

    uint4 H, L;
    split2(v[0] * inv, v[1] * inv, H.x, L.x);
    split2(v[2] * inv, v[3] * inv, H.y, L.y);
    split2(v[4] * inv, v[5] * inv, H.z, L.z);
    split2(v[6] * inv, v[7] * inv, H.w, L.w);
    const long long o = (long long)blockIdx.x * NS + tid * 8;
    *(uint4*)(Phi + o) = H;
    *(uint4*)(Plo + o) = L;
}

// ---------------------------------------------------------------------------
// Launcher.
// ---------------------------------------------------------------------------
extern "C" void kernel_launch(void* const* d_in, const int* in_sizes, int n_in,
                              void* d_out, int out_size)
{
    const float* X  = (const float*)d_in[0];
    const float* Wk = (const float*)d_in[1];
    const float* bk = (const float*)d_in[2];
    const float* Wq = (const float*)d_in[3];
    const float* bq = (const float*)d_in[4];
    const float* Wv = (const float*)d_in[5];
    const float* bv = (const float*)d_in[6];
    float* Y = (float*)d_out;

    __nv_bfloat16 *Xhi, *Xlo, *Whi, *Wlo, *Qhi, *Qlo, *Khi, *Klo, *Vthi, *Vtlo, *Phi, *Plo;
    float* Pp;
    cudaGetSymbolAddress((void**)&Xhi, g_Xhi);   cudaGetSymbolAddress((void**)&Xlo, g_Xlo);
    cudaGetSymbolAddress((void**)&Whi, g_Whi);   cudaGetSymbolAddress((void**)&Wlo, g_Wlo);
    cudaGetSymbolAddress((void**)&Qhi, g_Qhi);   cudaGetSymbolAddress((void**)&Qlo, g_Qlo);
    cudaGetSymbolAddress((void**)&Khi, g_Khi);   cudaGetSymbolAddress((void**)&Klo, g_Klo);
    cudaGetSymbolAddress((void**)&Vthi, g_Vthi); cudaGetSymbolAddress((void**)&Vtlo, g_Vtlo);
    cudaGetSymbolAddress((void**)&Phi, g_Phi);   cudaGetSymbolAddress((void**)&Plo, g_Plo);
    cudaGetSymbolAddress((void**)&Pp, g_P);

    cudaFuncSetAttribute(gemm_proj3, cudaFuncAttributeMaxDynamicSharedMemorySize, SMEM_TOTAL);
    cudaFuncSetAttribute(gemm_nt,    cudaFuncAttributeMaxDynamicSharedMemorySize, SMEM_TOTAL);

    const dim3 blk(128);

    // one fused split launch: X, Wk, Wq, Wv
    splitAll<<<(X4 + 3 * W4) / 256, 256>>>(X, Wk, Wq, Wv, Xhi, Xlo, Whi, Wlo);

    // All three projections in ONE launch (z=0 K, z=1 Q, z=2 Vt)
    {
        dim3 grid(NE / 128, BSN / 128, 3);
        gemm_proj3<<<grid, blk, SMEM_TOTAL>>>(
            Xhi, Xlo, Whi, Wlo, bk, bq, bv,
            Khi, Klo, Qhi, Qlo, Vthi, Vtlo);
    }
    // Scores: P[b,j,i] = Q_j . K_i / sqrt(S)  (M=N=2048, batched)
    {
        dim3 grid(NS / 128, NS / 128, NB);
        const float alpha = rsqrtf((float)NS);
        gemm_nt<<<grid, blk, SMEM_TOTAL>>>(
            Qhi, Qlo, Khi, Klo, Pp,
            NE, NE, NS, NE,
            (long long)NS * NE, (long long)NS * NE, (long long)NS * NS, alpha);
    }
    // Softmax over key index i -> bf16 hi/lo
    softmax2048<<<NB * NS, 256>>>(Pp, Phi, Plo);

    // Y = P @ Vt^T  (M=2048, N=1024, K=2048)
    {
        dim3 grid(NE / 128, NS / 128, NB);
        gemm_nt<<<grid, blk, SMEM_TOTAL>>>(
            Phi, Plo, Vthi, Vtlo, Y,
            NS, BSN, NE, NS,
            (long long)NS * NS, (long long)NS, (long long)NS * NE, 1.f);
    }
}

// round 13
// speedup vs baseline: 1.0705x; 1.0255x over previous
#include <cuda_runtime.h>
#include <cuda_bf16.h>
#include <math.h>
#include <stdint.h>

#define NB 4
#define NS 2048
#define NE 1024
#define BSN (NB * NS)

// ---------------- persistent scratch (no cudaMalloc allowed) ----------------
__device__ __nv_bfloat16 g_Xhi[BSN * NE], g_Xlo[BSN * NE];
__device__ __nv_bfloat16 g_Whi[3 * NE * NE], g_Wlo[3 * NE * NE];
__device__ __nv_bfloat16 g_Qhi[BSN * NE], g_Qlo[BSN * NE];
__device__ __nv_bfloat16 g_Khi[BSN * NE], g_Klo[BSN * NE];
__device__ __nv_bfloat16 g_Vthi[(size_t)NE * BSN], g_Vtlo[(size_t)NE * BSN];
__device__ float         g_P[(size_t)NB * NS * NS];
__device__ __nv_bfloat16 g_Phi[(size_t)NB * NS * NS], g_Plo[(size_t)NB * NS * NS];

// ---------------- helpers ----------------
__device__ __forceinline__ uint32_t smem_u32(const void* p) {
    uint32_t a;
    asm("{ .reg .u64 t; cvta.to.shared.u64 t, %1; cvt.u32.u64 %0, t; }" : "=r"(a) : "l"(p));
    return a;
}
__device__ __forceinline__ void ldsm4(uint32_t* r, uint32_t addr) {
    asm volatile("ldmatrix.sync.aligned.m8n8.x4.shared.b16 {%0,%1,%2,%3}, [%4];"
                 : "=r"(r[0]), "=r"(r[1]), "=r"(r[2]), "=r"(r[3]) : "r"(addr));
}
__device__ __forceinline__ void mma16816(float* c, const uint32_t* a, const uint32_t* b) {
    asm volatile("mma.sync.aligned.m16n8k16.row.col.f32.bf16.bf16.f32 "
                 "{%0,%1,%2,%3}, {%4,%5,%6,%7}, {%8,%9}, {%0,%1,%2,%3};"
                 : "+f"(c[0]), "+f"(c[1]), "+f"(c[2]), "+f"(c[3])
                 : "r"(a[0]), "r"(a[1]), "r"(a[2]), "r"(a[3]), "r"(b[0]), "r"(b[1]));
}
__device__ __forceinline__ void cpa16(uint32_t s, const void* g) {
    asm volatile("cp.async.cg.shared.global [%0], [%1], 16;" :: "r"(s), "l"(g));
}
#define CP_COMMIT() asm volatile("cp.async.commit_group;" ::: "memory")
#define CP_WAIT(N)  asm volatile("cp.async.wait_group %0;" :: "n"(N) : "memory")

__device__ __forceinline__ uint32_t pack_bf2(float a, float b) {
    unsigned short ua = __bfloat16_as_ushort(__float2bfloat16(a));
    unsigned short ub = __bfloat16_as_ushort(__float2bfloat16(b));
    return (uint32_t)ua | ((uint32_t)ub << 16);
}
__device__ __forceinline__ void split2(float a, float b, uint32_t& h, uint32_t& l) {
    h = pack_bf2(a, b);
    float ha = __uint_as_float(h << 16);
    float hb = __uint_as_float(h & 0xFFFF0000u);
    l = pack_bf2(a - ha, b - hb);
}

// smem: BK=32 -> unpadded 64 B rows with XOR quad swizzle (q ^= (row>>1)&3).
#define T_A_HI 0
#define T_A_LO 8192
#define T_B_HI 16384
#define T_B_LO 24576
#define STAGE  32768
#define NSTAGE 3
#define SMEM_TOTAL (NSTAGE * STAGE)   // 98304 B per CTA -> 2 CTAs/SM (192 KB)

// ---------------------------------------------------------------------------
// GEMM body: C = alpha*A*B^T (+bias), bf16 hi/lo 3-term split.
// CTA tile 128x128, BK=32, 256 threads (8 warps 2Mx4N), warp tile 64x32.
// 16 warps/SM (2 CTAs). 3-stage cp.async, CP_WAIT(1), staging issued between
// kh0 and kh1 (interleaves with MMA drain). One __syncthreads per chunk.
// biasMode: 0 none, 1 bias[col], 2 bias[row]. OUTMODE: 0 fp32 C, 1 bf16 hi/lo.
// A/B pointers pre-offset to the CTA tile.
// ---------------------------------------------------------------------------
template <int OUTMODE>
__device__ __forceinline__ void gemm_body(
    const __nv_bfloat16* __restrict__ Ahi, const __nv_bfloat16* __restrict__ Alo,
    const __nv_bfloat16* __restrict__ Bhi, const __nv_bfloat16* __restrict__ Blo,
    int lda, int ldb, int Kdim,
    const float* __restrict__ bias, int biasMode,
    float* __restrict__ C, __nv_bfloat16* __restrict__ Chi, __nv_bfloat16* __restrict__ Clo,
    long long cbase, int ldc, int row0, int col0, float alpha)
{
    extern __shared__ char smem[];
    const uint32_t sb = smem_u32(smem);
    const int tid = threadIdx.x;
    const int lane = tid & 31;
    const int wid = tid >> 5;
    const int warpM = (wid & 1) * 64;     // 2 warps in M, 64 rows each
    const int warpN = (wid >> 1) * 32;    // 4 warps in N, 32 cols each

    float acc[4][4][4];
#pragma unroll
    for (int m = 0; m < 4; m++)
#pragma unroll
        for (int n = 0; n < 4; n++)
#pragma unroll
            for (int q = 0; q < 4; q++) acc[m][n][q] = 0.f;

    // strength-reduced staging state (256 threads: 2 quads per thread per tensor)
    const int r0 = tid >> 2, q0 = tid & 3;
    const uint32_t so0 = (uint32_t)(r0 * 64 + ((q0 ^ ((r0 >> 1) & 3)) * 16));
    const __nv_bfloat16* gAh = Ahi + (long long)r0 * lda + q0 * 8;
    const __nv_bfloat16* gAl = Alo + (long long)r0 * lda + q0 * 8;
    const __nv_bfloat16* gBh = Bhi + (long long)r0 * ldb + q0 * 8;
    const __nv_bfloat16* gBl = Blo + (long long)r0 * ldb + q0 * 8;
    const long long stepA = 64LL * lda;   // rows advance by 64 per p step
    const long long stepB = 64LL * ldb;

    auto issueStage = [&](uint32_t st) {
#pragma unroll
        for (int p = 0; p < 2; p++) {
            const uint32_t so = so0 + (uint32_t)(p * 4096);   // +64 rows * 64 B
            cpa16(st + T_A_HI + so, gAh + p * stepA);
            cpa16(st + T_A_LO + so, gAl + p * stepA);
            cpa16(st + T_B_HI + so, gBh + p * stepB);
            cpa16(st + T_B_LO + so, gBl + p * stepB);
        }
        gAh += 32; gAl += 32; gBh += 32; gBl += 32;
        CP_COMMIT();
    };

    // ldmatrix lane addressing
    const int lr = lane & 15;
    const int lq = lane >> 4;
    const int lsw = (lr >> 1) & 3;
    const uint32_t rowA = (uint32_t)(warpM + lr);
    const uint32_t rowB = (uint32_t)(warpN + lr);

    // one kh half-chunk: 12 LDSM + 48 MMAs
    auto khPart = [&](uint32_t stb, int kh) {
        const uint32_t qb = (uint32_t)(((kh * 2 + lq) ^ lsw) * 16);
        uint32_t ahi[4][4], alo[4][4], bhi[4][2], blo[4][2];
#pragma unroll
        for (int mt = 0; mt < 4; mt++) {
            ldsm4(ahi[mt], stb + T_A_HI + (rowA + mt * 16) * 64 + qb);
            ldsm4(alo[mt], stb + T_A_LO + (rowA + mt * 16) * 64 + qb);
        }
#pragma unroll
        for (int np = 0; np < 2; np++) {
            uint32_t t[4];
            ldsm4(t, stb + T_B_HI + (rowB + np * 16) * 64 + qb);
            bhi[2 * np][0] = t[0]; bhi[2 * np][1] = t[2];
            bhi[2 * np + 1][0] = t[1]; bhi[2 * np + 1][1] = t[3];
            ldsm4(t, stb + T_B_LO + (rowB + np * 16) * 64 + qb);
            blo[2 * np][0] = t[0]; blo[2 * np][1] = t[2];
            blo[2 * np + 1][0] = t[1]; blo[2 * np + 1][1] = t[3];
        }
#pragma unroll
        for (int mt = 0; mt < 4; mt++)
#pragma unroll
            for (int nt = 0; nt < 4; nt++) mma16816(acc[mt][nt], ahi[mt], bhi[nt]);
#pragma unroll
        for (int mt = 0; mt < 4; mt++)
#pragma unroll
            for (int nt = 0; nt < 4; nt++) mma16816(acc[mt][nt], ahi[mt], blo[nt]);
#pragma unroll
        for (int mt = 0; mt < 4; mt++)
#pragma unroll
            for (int nt = 0; nt < 4; nt++) mma16816(acc[mt][nt], alo[mt], bhi[nt]);
    };

    const int CH = Kdim >> 5;      // BK = 32
    const uint32_t sTop = sb + (NSTAGE - 1) * STAGE;
    uint32_t stW = sb, stR = sb;

    issueStage(stW); stW += STAGE;
    issueStage(stW); stW += STAGE;

    for (int c = 0; c < CH; c++) {
        if (c + 1 < CH) { CP_WAIT(1); } else { CP_WAIT(0); }
        __syncthreads();
        khPart(stR, 0);                 // MMAs first: tensor pipe fills
        if (c + 2 < CH) {               // staging burst hides under MMA drain
            issueStage(stW);
            stW = (stW == sTop) ? sb : stW + STAGE;
        }
        khPart(stR, 1);
        stR = (stR == sTop) ? sb : stR + STAGE;
        // no tail sync: issue at iter c targets buffer (c-1)%3, which all
        // warps finished computing before this iteration's head sync.
    }

    // ---- epilogue ----
    const int g = lane >> 2, tg = lane & 3;
#pragma unroll
    for (int mt = 0; mt < 4; mt++) {
        const int row = row0 + warpM + mt * 16 + g;
        float rb0 = 0.f, rb8 = 0.f;
        if (biasMode == 2) { rb0 = bias[row]; rb8 = bias[row + 8]; }
#pragma unroll
        for (int nt = 0; nt < 4; nt++) {
            const int col = col0 + warpN + nt * 8 + tg * 2;
            float c0 = acc[mt][nt][0] * alpha;
            float c1 = acc[mt][nt][1] * alpha;
            float c2 = acc[mt][nt][2] * alpha;
            float c3 = acc[mt][nt][3] * alpha;
            if (biasMode == 1) {
                const float b0 = bias[col], b1 = bias[col + 1];
                c0 += b0; c1 += b1; c2 += b0; c3 += b1;
            } else if (biasMode == 2) {
                c0 += rb0; c1 += rb0; c2 += rb8; c3 += rb8;
            }
            const long long i0 = cbase + (long long)row * ldc + col;
            const long long i1 = i0 + (long long)8 * ldc;
            if (OUTMODE == 0) {
                *(float2*)(C + i0) = make_float2(c0, c1);
                *(float2*)(C + i1) = make_float2(c2, c3);
            } else {
                uint32_t h, l;
                split2(c0, c1, h, l);
                *(uint32_t*)(Chi + i0) = h; *(uint32_t*)(Clo + i0) = l;
                split2(c2, c3, h, l);
                *(uint32_t*)(Chi + i1) = h; *(uint32_t*)(Clo + i1) = l;
            }
        }
    }
}

// ---------------------------------------------------------------------------
// Fused projection kernel: z=0 -> K, z=1 -> Q, z=2 -> Vt (remapped tiles).
// grid (8, 64, 3), 256 threads.
// ---------------------------------------------------------------------------
__global__ void __launch_bounds__(256, 2)
gemm_proj3(const __nv_bfloat16* __restrict__ Xhi, const __nv_bfloat16* __restrict__ Xlo,
           const __nv_bfloat16* __restrict__ Whi, const __nv_bfloat16* __restrict__ Wlo,
           const float* __restrict__ bk, const float* __restrict__ bq,
           const float* __restrict__ bv,
           __nv_bfloat16* __restrict__ Khi, __nv_bfloat16* __restrict__ Klo,
           __nv_bfloat16* __restrict__ Qhi, __nv_bfloat16* __restrict__ Qlo,
           __nv_bfloat16* __restrict__ Vthi, __nv_bfloat16* __restrict__ Vtlo)
{
    const int WN = NE * NE;
    const int z = blockIdx.z;
    if (z < 2) {
        // K or Q = X @ W^T + b(col): M = BSN, N = NE
        const int row0 = blockIdx.y * 128;
        const int col0 = blockIdx.x * 128;
        const long long aoff = (long long)row0 * NE;
        const long long boff = (long long)z * WN + (long long)col0 * NE;
        gemm_body<1>(Xhi + aoff, Xlo + aoff, Whi + boff, Wlo + boff,
                     NE, NE, NE,
                     (z == 0) ? bk : bq, 1,
                     nullptr,
                     (z == 0) ? Khi : Qhi, (z == 0) ? Klo : Qlo,
                     0, NE, row0, col0, 1.f);
    } else {
        // Vt = Wv @ X^T + bv(row): M = NE, N = BSN
        const int tx = blockIdx.x + (blockIdx.y & 7) * 8;  // 0..63 (N tiles)
        const int ty = blockIdx.y >> 3;                    // 0..7  (M tiles)
        const int row0 = ty * 128;
        const int col0 = tx * 128;
        const long long aoff = 2LL * WN + (long long)row0 * NE;
        const long long boff = (long long)col0 * NE;
        gemm_body<1>(Whi + aoff, Wlo + aoff, Xhi + boff, Xlo + boff,
                     NE, NE, NE,
                     bv, 2,
                     nullptr, Vthi, Vtlo,
                     0, BSN, row0, col0, 1.f);
    }
}

// ---------------------------------------------------------------------------
// Plain batched NT GEMM wrapper (fp32 out, no bias).
// ---------------------------------------------------------------------------
__global__ void __launch_bounds__(256, 2)
gemm_nt(const __nv_bfloat16* __restrict__ Ahi, const __nv_bfloat16* __restrict__ Alo,
        const __nv_bfloat16* __restrict__ Bhi, const __nv_bfloat16* __restrict__ Blo,
        float* __restrict__ C,
        int lda, int ldb, int ldc, int Kdim,
        long long sA, long long sB, long long sC, float alpha)
{
    const int row0 = blockIdx.y * 128;
    const int col0 = blockIdx.x * 128;
    const long long aoff = (long long)blockIdx.z * sA + (long long)row0 * lda;
    const long long boff = (long long)blockIdx.z * sB + (long long)col0 * ldb;
    gemm_body<0>(Ahi + aoff, Alo + aoff, Bhi + boff, Blo + boff,
                 lda, ldb, Kdim,
                 nullptr, 0,
                 C, nullptr, nullptr,
                 (long long)blockIdx.z * sC, ldc, row0, col0, alpha);
}

// ---------------------------------------------------------------------------
// Fused fp32 -> bf16 hi/lo split over [X | Wk | Wq | Wv] (one launch).
// ---------------------------------------------------------------------------
#define X4  (BSN * NE / 4)
#define W4  (NE * NE / 4)
__global__ __launch_bounds__(256)
void splitAll(const float* __restrict__ X,
              const float* __restrict__ Wk, const float* __restrict__ Wq,
              const float* __restrict__ Wv,
              __nv_bfloat16* __restrict__ Xhi, __nv_bfloat16* __restrict__ Xlo,
              __nv_bfloat16* __restrict__ Whi, __nv_bfloat16* __restrict__ Wlo)
{
    const int i = blockIdx.x * 256 + threadIdx.x;
    const float* src;
    __nv_bfloat16 *hi, *lo;
    int j;
    if (i < X4)                { src = X;  hi = Xhi;          lo = Xlo;          j = i; }
    else if (i < X4 + W4)      { src = Wk; hi = Whi;          lo = Wlo;          j = i - X4; }
    else if (i < X4 + 2 * W4)  { src = Wq; hi = Whi + NE*NE;  lo = Wlo + NE*NE;  j = i - X4 - W4; }
    else                       { src = Wv; hi = Whi + 2*NE*NE; lo = Wlo + 2*NE*NE; j = i - X4 - 2*W4; }
    const float4 v = ((const float4*)src)[j];
    uint32_t h01, l01, h23, l23;
    split2(v.x, v.y, h01, l01);
    split2(v.z, v.w, h23, l23);
    ((uint2*)hi)[j] = make_uint2(h01, h23);
    ((uint2*)lo)[j] = make_uint2(l01, l23);
}

// ---------------------------------------------------------------------------
// Row softmax over 2048, emits bf16 hi/lo. One block (256 thr) per row.
// ---------------------------------------------------------------------------
__global__ __launch_bounds__(256)
void softmax2048(const float* __restrict__ P, __nv_bfloat16* __restrict__ Phi,
                 __nv_bfloat16* __restrict__ Plo)
{
    __shared__ float red[32];
    const float* p = P + (long long)blockIdx.x * NS;
    const int tid = threadIdx.x;

    float v[8];
    {
        const float4 a = *(const float4*)(p + tid * 8);
        const float4 b = *(const float4*)(p + tid * 8 + 4);
        v[0] = a.x; v[1] = a.y; v[2] = a.z; v[3] = a.w;
        v[4] = b.x; v[5] = b.y; v[6] = b.z; v[7] = b.w;
    }

    float m = v[0];
#pragma unroll
    for (int i = 1; i < 8; i++) m = fmaxf(m, v[i]);
#pragma unroll
    for (int o = 16; o > 0; o >>= 1) m = fmaxf(m, __shfl_xor_sync(0xffffffffu, m, o));
    if ((tid & 31) == 0) red[tid >> 5] = m;
    __syncthreads();
    if (tid < 32) {
        float t = (tid < 8) ? red[tid] : -INFINITY;
#pragma unroll
        for (int o = 4; o > 0; o >>= 1) t = fmaxf(t, __shfl_xor_sync(0xffffffffu, t, o));
        if (tid == 0) red[0] = t;
    }
    __syncthreads();
    m = red[0];
    __syncthreads();

    float s = 0.f;
#pragma unroll
    for (int i = 0; i < 8; i++) { v[i] = __expf(v[i] - m); s += v[i]; }
#pragma unroll
    for (int o = 16; o > 0; o >>= 1) s += __shfl_xor_sync(0xffffffffu, s, o);
    if ((tid & 31) == 0) red[tid >> 5] = s;
    __syncthreads();
    if (tid < 32) {
        float t = (tid < 8) ? red[tid] : 0.f;
#pragma unroll
        for (int o = 4; o > 0; o >>= 1) t += __shfl_xor_sync(0xffffffffu, t, o);
        if (tid == 0) red[0] = t;
    }
    __syncthreads();
    const float inv = 1.f / red[0];

    uint4 H, L;
    split2(v[0] * inv, v[1] * inv, H.x, L.x);
    split2(v[2] * inv, v[3] * inv, H.y, L.y);
    split2(v[4] * inv, v[5] * inv, H.z, L.z);
    split2(v[6] * inv, v[7] * inv, H.w, L.w);
    const long long o = (long long)blockIdx.x * NS + tid * 8;
    *(uint4*)(Phi + o) = H;
    *(uint4*)(Plo + o) = L;
}

// ---------------------------------------------------------------------------
// Launcher.
// ---------------------------------------------------------------------------
extern "C" void kernel_launch(void* const* d_in, const int* in_sizes, int n_in,
                              void* d_out, int out_size)
{
    const float* X  = (const float*)d_in[0];
    const float* Wk = (const float*)d_in[1];
    const float* bk = (const float*)d_in[2];
    const float* Wq = (const float*)d_in[3];
    const float* bq = (const float*)d_in[4];
    const float* Wv = (const float*)d_in[5];
    const float* bv = (const float*)d_in[6];
    float* Y = (float*)d_out;

    __nv_bfloat16 *Xhi, *Xlo, *Whi, *Wlo, *Qhi, *Qlo, *Khi, *Klo, *Vthi, *Vtlo, *Phi, *Plo;
    float* Pp;
    cudaGetSymbolAddress((void**)&Xhi, g_Xhi);   cudaGetSymbolAddress((void**)&Xlo, g_Xlo);
    cudaGetSymbolAddress((void**)&Whi, g_Whi);   cudaGetSymbolAddress((void**)&Wlo, g_Wlo);
    cudaGetSymbolAddress((void**)&Qhi, g_Qhi);   cudaGetSymbolAddress((void**)&Qlo, g_Qlo);
    cudaGetSymbolAddress((void**)&Khi, g_Khi);   cudaGetSymbolAddress((void**)&Klo, g_Klo);
    cudaGetSymbolAddress((void**)&Vthi, g_Vthi); cudaGetSymbolAddress((void**)&Vtlo, g_Vtlo);
    cudaGetSymbolAddress((void**)&Phi, g_Phi);   cudaGetSymbolAddress((void**)&Plo, g_Plo);
    cudaGetSymbolAddress((void**)&Pp, g_P);

    cudaFuncSetAttribute(gemm_proj3, cudaFuncAttributeMaxDynamicSharedMemorySize, SMEM_TOTAL);
    cudaFuncSetAttribute(gemm_nt,    cudaFuncAttributeMaxDynamicSharedMemorySize, SMEM_TOTAL);

    const dim3 blk(256);

    // one fused split launch: X, Wk, Wq, Wv
    splitAll<<<(X4 + 3 * W4) / 256, 256>>>(X, Wk, Wq, Wv, Xhi, Xlo, Whi, Wlo);

    // All three projections in ONE launch (z=0 K, z=1 Q, z=2 Vt)
    {
        dim3 grid(NE / 128, BSN / 128, 3);
        gemm_proj3<<<grid, blk, SMEM_TOTAL>>>(
            Xhi, Xlo, Whi, Wlo, bk, bq, bv,
            Khi, Klo, Qhi, Qlo, Vthi, Vtlo);
    }
    // Scores: P[b,j,i] = Q_j . K_i / sqrt(S)  (M=N=2048, batched)
    {
        dim3 grid(NS / 128, NS / 128, NB);
        const float alpha = rsqrtf((float)NS);
        gemm_nt<<<grid, blk, SMEM_TOTAL>>>(
            Qhi, Qlo, Khi, Klo, Pp,
            NE, NE, NS, NE,
            (long long)NS * NE, (long long)NS * NE, (long long)NS * NS, alpha);
    }
    // Softmax over key index i -> bf16 hi/lo
    softmax2048<<<NB * NS, 256>>>(Pp, Phi, Plo);

    // Y = P @ Vt^T  (M=2048, N=1024, K=2048)
    {
        dim3 grid(NE / 128, NS / 128, NB);
        gemm_nt<<<grid, blk, SMEM_TOTAL>>>(
            Phi, Plo, Vthi, Vtlo, Y,
            NS, BSN, NE, NS,
            (long long)NS * NS, (long long)NS, (long long)NS * NE, 1.f);
    }
}